// round 5
// baseline (speedup 1.0000x reference)
#include <cuda_runtime.h>
#include <cuda_fp16.h>
#include <math.h>

// ---------------- problem constants ----------------
#define MPTS   32768
#define NPTS   (MPTS * 8)          // 262144 upsampled points
#define NV     9
#define NC     24
#define NH     120
#define NW     160
#define CPRE   50
#define CIN    (NC + 1 + CPRE)     // 75
#define CHID   24
#define HW     (NH * NW)
#define VHW    (NV * HW)
#define VOXSZ  0.04f
#define TQ     (NPTS / 4)          // 65536 threads in MLP, 4 points each

// ---------------- scratch (device globals; no allocation) ----------------
__device__ __align__(16) __half g_featTh[VHW * NC + 64];  // feats (V,H,W,C) fp16, +pad (zero-init)
__device__ __align__(16) float  g_features[NPTS * NC];    // per-point mean features
__device__ float  g_z[NPTS];
__device__ double g_red[3];                               // sum(z*pos), sum(z^2*pos), sum(pos)

__constant__ int c_off[8][3] = {
    {0,0,0},{1,0,0},{0,1,0},{0,0,1},{1,1,0},{1,0,1},{0,1,1},{1,1,1}
};

// ---------------- helpers ----------------
typedef unsigned long long u64;
__device__ __forceinline__ u64 pack2(float a, float b) {
    u64 r; asm("mov.b64 %0, {%1, %2};" : "=l"(r) : "f"(a), "f"(b)); return r;
}
__device__ __forceinline__ u64 fma2(u64 a, u64 b, u64 c) {
    u64 d; asm("fma.rn.f32x2 %0, %1, %2, %3;" : "=l"(d) : "l"(a), "l"(b), "l"(c)); return d;
}
__device__ __forceinline__ float2 unpack2(u64 v) {
    float2 f; asm("mov.b64 {%0, %1}, %2;" : "=f"(f.x), "=f"(f.y) : "l"(v)); return f;
}
// reinterpret u32 as __half2 (scalar bit-cast; always register-promoted)
__device__ __forceinline__ __half2 u2h(unsigned u) {
    __half2 h;
    *reinterpret_cast<unsigned*>(&h) = u;
    return h;
}

// ---------------- kernel 1: transpose (V,C,H,W) fp32 -> (V,H,W,C) fp16; zero g_red ----------------
__global__ void k_transpose(const float* __restrict__ feats) {
    int tid = blockIdx.x * blockDim.x + threadIdx.x;
    if (tid == 0) { g_red[0] = 0.0; g_red[1] = 0.0; g_red[2] = 0.0; }
    if (tid >= VHW * 3) return;
    int pix = tid / 3;
    int c0  = (tid - pix * 3) * 8;
    int v   = pix / HW;
    int rem = pix - v * HW;
    const float* src = feats + (size_t)v * NC * HW + (size_t)c0 * HW + rem;
    float vals[8];
#pragma unroll
    for (int c = 0; c < 8; c++) vals[c] = src[(size_t)c * HW];   // coalesced across x
    __half2 h[4];
#pragma unroll
    for (int j = 0; j < 4; j++) h[j] = __floats2half2_rn(vals[2*j], vals[2*j+1]);
    reinterpret_cast<uint4*>(g_featTh)[pix * 3 + (c0 >> 3)] = *reinterpret_cast<uint4*>(h);
}

// ---------------- kernel 2: back-projection + per-point stats ----------------
__global__ __launch_bounds__(256) void k_backproject(
    const int*   __restrict__ pre_coords,   // (M,4) int32
    const float* __restrict__ KRcam,        // (V,1,4,4)
    const float* __restrict__ origin,       // (3,)
    const float* __restrict__ w2ac,         // (1,4,4)
    float*       __restrict__ d_out)        // [out 2N | count N | r_coords 4N]
{
    __shared__ float sKR[NV * 16];
    __shared__ float sW2[12];
    __shared__ float sOrg[3];
    int t = threadIdx.x;
    if (t < NV * 16) sKR[t] = KRcam[t];
    if (t < 12)      sW2[t] = w2ac[t];
    if (t < 3)       sOrg[t] = origin[t];
    __syncthreads();

    int n = blockIdx.x * 256 + t;
    int m = n >> 3, k = n & 7;

    int cx = pre_coords[m * 4 + 1] + c_off[k][0];
    int cy = pre_coords[m * 4 + 2] + c_off[k][1];
    int cz = pre_coords[m * 4 + 3] + c_off[k][2];
    float wx = (float)cx * VOXSZ + sOrg[0];
    float wy = (float)cy * VOXSZ + sOrg[1];
    float wz = (float)cz * VOXSZ + sOrg[2];

    // r_coords
    {
        float4 rc;
        rc.x = sW2[0]*wx + sW2[1]*wy + sW2[2]*wz + sW2[3];
        rc.y = sW2[4]*wx + sW2[5]*wy + sW2[6]*wz + sW2[7];
        rc.z = sW2[8]*wx + sW2[9]*wy + sW2[10]*wz + sW2[11];
        rc.w = 0.0f;
        reinterpret_cast<float4*>(d_out + 3 * NPTS)[n] = rc;
    }

    float a[NC];
#pragma unroll
    for (int j = 0; j < NC; j++) a[j] = 0.f;
    float zsum = 0.f;
    int   cnt  = 0;

    const uint4* fb = reinterpret_cast<const uint4*>(g_featTh);

#pragma unroll 1
    for (int v = 0; v < NV; v++) {
        const float* R = sKR + v * 16;
        float ix = R[0]*wx + R[1]*wy + R[2]*wz  + R[3];
        float iy = R[4]*wx + R[5]*wy + R[6]*wz  + R[7];
        float iz = R[8]*wx + R[9]*wy + R[10]*wz + R[11];
        float sz = (fabsf(iz) > 1e-9f) ? iz : 1e-9f;
        float px = ix / sz;
        float py = iy / sz;
        bool msk = (px >= 0.f) && (px <= (float)(NW - 1)) &&
                   (py >= 0.f) && (py <= (float)(NH - 1)) && (iz > 0.f);
        if (!msk) continue;

        float fx0 = floorf(px), fy0 = floorf(py);
        float ax = px - fx0,    ay = py - fy0;
        int ix0 = (int)fx0,     iy0 = (int)fy0;
        float okx = (ix0 + 1 < NW) ? 1.f : 0.f;
        float oky = (iy0 + 1 < NH) ? 1.f : 0.f;
        int iy1 = min(iy0 + 1, NH - 1);

        // bilinear weights -> half2 (4 small converts per view)
        __half2 W00 = __float2half2_rn((1.f - ax) * (1.f - ay));
        __half2 W10 = __float2half2_rn(ax * (1.f - ay) * okx);
        __half2 W01 = __float2half2_rn((1.f - ax) * ay * oky);
        __half2 W11 = __float2half2_rn(ax * ay * okx * oky);

        // contiguous 96B span covers both x0 and x1 (pixel = 48B fp16)
        int b_top = ((v * NH + iy0) * NW + ix0) * 3;
        int b_bot = ((v * NH + iy1) * NW + ix0) * 3;

#pragma unroll
        for (int j = 0; j < 3; j++) {               // channels 8j..8j+7
            uint4 T0 = fb[b_top + j];               // x0
            uint4 T1 = fb[b_top + j + 3];           // x1
            uint4 B0 = fb[b_bot + j];
            uint4 B1 = fb[b_bot + j + 3];
            int cb = 8 * j;
            // weighted sum entirely in half pipe (HMUL2/HFMA2, full rate)
            __half2 r0 = __hmul2(u2h(T0.x), W00);
            r0 = __hfma2(u2h(T1.x), W10, r0);
            r0 = __hfma2(u2h(B0.x), W01, r0);
            r0 = __hfma2(u2h(B1.x), W11, r0);
            __half2 r1 = __hmul2(u2h(T0.y), W00);
            r1 = __hfma2(u2h(T1.y), W10, r1);
            r1 = __hfma2(u2h(B0.y), W01, r1);
            r1 = __hfma2(u2h(B1.y), W11, r1);
            __half2 r2 = __hmul2(u2h(T0.z), W00);
            r2 = __hfma2(u2h(T1.z), W10, r2);
            r2 = __hfma2(u2h(B0.z), W01, r2);
            r2 = __hfma2(u2h(B1.z), W11, r2);
            __half2 r3 = __hmul2(u2h(T0.w), W00);
            r3 = __hfma2(u2h(T1.w), W10, r3);
            r3 = __hfma2(u2h(B0.w), W01, r3);
            r3 = __hfma2(u2h(B1.w), W11, r3);
            // single convert of the per-view result, fp32 accumulate
            float2 f0 = __half22float2(r0);
            float2 f1 = __half22float2(r1);
            float2 f2 = __half22float2(r2);
            float2 f3 = __half22float2(r3);
            a[cb+0] += f0.x;  a[cb+1] += f0.y;
            a[cb+2] += f1.x;  a[cb+3] += f1.y;
            a[cb+4] += f2.x;  a[cb+5] += f2.y;
            a[cb+6] += f3.x;  a[cb+7] += f3.y;
        }
        zsum += iz;
        cnt  += 1;
    }

    float denom = fmaxf((float)cnt, 1.f);
    float inv   = 1.f / denom;
    float4* fdst = reinterpret_cast<float4*>(g_features) + (size_t)n * 6;
#pragma unroll
    for (int j = 0; j < 6; j++)
        fdst[j] = make_float4(a[4*j]*inv, a[4*j+1]*inv, a[4*j+2]*inv, a[4*j+3]*inv);

    float zv = zsum * inv;
    g_z[n] = zv;
    d_out[2 * NPTS + n] = (float)cnt;

    bool  pos = zv > 0.f;
    float r0 = pos ? zv : 0.f;
    float r1 = pos ? zv * zv : 0.f;
    float r2 = pos ? 1.f : 0.f;
#pragma unroll
    for (int o = 16; o > 0; o >>= 1) {
        r0 += __shfl_down_sync(0xffffffffu, r0, o);
        r1 += __shfl_down_sync(0xffffffffu, r1, o);
        r2 += __shfl_down_sync(0xffffffffu, r2, o);
    }
    __shared__ float s0[8], s1[8], s2[8];
    int w = t >> 5, lane = t & 31;
    if (lane == 0) { s0[w] = r0; s1[w] = r1; s2[w] = r2; }
    __syncthreads();
    if (t == 0) {
        float t0 = 0.f, t1 = 0.f, t2 = 0.f;
#pragma unroll
        for (int i = 0; i < 8; i++) { t0 += s0[i]; t1 += s1[i]; t2 += s2[i]; }
        atomicAdd(&g_red[0], (double)t0);
        atomicAdd(&g_red[1], (double)t1);
        atomicAdd(&g_red[2], (double)t2);
    }
}

// ---------------- kernel 3: z-norm + MLP heads (4 points/thread, f32x2) ----------------
__device__ __forceinline__ void mlp_row(u64* A01, u64* A23, u64 fab, u64 fcd,
                                        const float4* __restrict__ wr) {
#pragma unroll
    for (int q = 0; q < 6; q++) {
        float4 w = wr[q];
        u64 w0 = pack2(w.x, w.x);
        A01[4*q+0] = fma2(fab, w0, A01[4*q+0]); A23[4*q+0] = fma2(fcd, w0, A23[4*q+0]);
        u64 w1 = pack2(w.y, w.y);
        A01[4*q+1] = fma2(fab, w1, A01[4*q+1]); A23[4*q+1] = fma2(fcd, w1, A23[4*q+1]);
        u64 w2 = pack2(w.z, w.z);
        A01[4*q+2] = fma2(fab, w2, A01[4*q+2]); A23[4*q+2] = fma2(fcd, w2, A23[4*q+2]);
        u64 w3 = pack2(w.w, w.w);
        A01[4*q+3] = fma2(fab, w3, A01[4*q+3]); A23[4*q+3] = fma2(fcd, w3, A23[4*q+3]);
    }
}

__global__ __launch_bounds__(128) void k_mlp(
    const float* __restrict__ pre_feat,
    const float* __restrict__ W_sp,
    const float* __restrict__ b_sp,
    const float* __restrict__ W_t,
    const float* __restrict__ b_t,
    const float* __restrict__ W_o,
    const float* __restrict__ b_o,
    float*       __restrict__ d_out)
{
    __shared__ float4 sW[CIN * 6];
    __shared__ float  sWt[CHID], sWo[CHID], sB[CHID];
    int t = threadIdx.x;
    const float4* Wv = reinterpret_cast<const float4*>(W_sp);
    for (int i = t; i < CIN * 6; i += 128) sW[i] = Wv[i];
    if (t < CHID) { sWt[t] = W_t[t]; sWo[t] = W_o[t]; sB[t] = b_sp[t]; }
    __syncthreads();

    double npos  = fmax(g_red[2], 1.0);
    double zmean = g_red[0] / npos;
    double var   = g_red[1] - zmean * zmean * npos;
    float  znorm = (float)sqrt(fmax(var, 0.0)) + 1e-5f;
    float  zmf   = (float)zmean;

    int p0 = blockIdx.x * 128 + t;   // handles points p0 + k*TQ, k=0..3

    u64 A01[CHID], A23[CHID];
#pragma unroll
    for (int j = 0; j < CHID; j++) {
        u64 bb = pack2(sB[j], sB[j]);
        A01[j] = bb; A23[j] = bb;
    }

    // features (channels 0..23)
    const float4* f0 = reinterpret_cast<const float4*>(g_features) + (size_t)p0 * 6;
    const float4* f1 = f0 + (size_t)TQ * 6;
    const float4* f2 = f1 + (size_t)TQ * 6;
    const float4* f3 = f2 + (size_t)TQ * 6;
#pragma unroll
    for (int j4 = 0; j4 < 6; j4++) {
        float4 F0 = f0[j4], F1 = f1[j4], F2 = f2[j4], F3 = f3[j4];
        mlp_row(A01, A23, pack2(F0.x, F1.x), pack2(F2.x, F3.x), sW + (4*j4+0)*6);
        mlp_row(A01, A23, pack2(F0.y, F1.y), pack2(F2.y, F3.y), sW + (4*j4+1)*6);
        mlp_row(A01, A23, pack2(F0.z, F1.z), pack2(F2.z, F3.z), sW + (4*j4+2)*6);
        mlp_row(A01, A23, pack2(F0.w, F1.w), pack2(F2.w, F3.w), sW + (4*j4+3)*6);
    }
    // zn (channel 24)
    {
        float z0 = g_z[p0], z1 = g_z[p0 + TQ], z2 = g_z[p0 + 2*TQ], z3 = g_z[p0 + 3*TQ];
        float n0 = (z0 > 0.f) ? (z0 - zmf) / znorm : 0.f;
        float n1 = (z1 > 0.f) ? (z1 - zmf) / znorm : 0.f;
        float n2 = (z2 > 0.f) ? (z2 - zmf) / znorm : 0.f;
        float n3 = (z3 > 0.f) ? (z3 - zmf) / znorm : 0.f;
        mlp_row(A01, A23, pack2(n0, n1), pack2(n2, n3), sW + NC * 6);
    }
    // pre_feat (channels 25..74)
    {
        const float2* q0 = reinterpret_cast<const float2*>(pre_feat + (size_t)( p0          >> 3) * CPRE);
        const float2* q1 = reinterpret_cast<const float2*>(pre_feat + (size_t)((p0 +   TQ) >> 3) * CPRE);
        const float2* q2 = reinterpret_cast<const float2*>(pre_feat + (size_t)((p0 + 2*TQ) >> 3) * CPRE);
        const float2* q3 = reinterpret_cast<const float2*>(pre_feat + (size_t)((p0 + 3*TQ) >> 3) * CPRE);
#pragma unroll
        for (int i = 0; i < CPRE / 2; i++) {
            float2 g0 = q0[i], g1 = q1[i], g2 = q2[i], g3 = q3[i];
            mlp_row(A01, A23, pack2(g0.x, g1.x), pack2(g2.x, g3.x), sW + (NC + 1 + 2*i + 0) * 6);
            mlp_row(A01, A23, pack2(g0.y, g1.y), pack2(g2.y, g3.y), sW + (NC + 1 + 2*i + 1) * 6);
        }
    }

    // relu + heads
    float bt = b_t[0], bo = b_o[0];
    float ts0 = bt, ts1 = bt, ts2 = bt, ts3 = bt;
    float oc0 = bo, oc1 = bo, oc2 = bo, oc3 = bo;
#pragma unroll
    for (int j = 0; j < CHID; j++) {
        float2 ab = unpack2(A01[j]);
        float2 cd = unpack2(A23[j]);
        float h0 = fmaxf(ab.x, 0.f), h1 = fmaxf(ab.y, 0.f);
        float h2 = fmaxf(cd.x, 0.f), h3 = fmaxf(cd.y, 0.f);
        float wt = sWt[j], wo = sWo[j];
        ts0 += h0 * wt; ts1 += h1 * wt; ts2 += h2 * wt; ts3 += h3 * wt;
        oc0 += h0 * wo; oc1 += h1 * wo; oc2 += h2 * wo; oc3 += h3 * wo;
    }
    float2* out = reinterpret_cast<float2*>(d_out);
    out[p0         ] = make_float2(ts0, oc0);
    out[p0 +   TQ  ] = make_float2(ts1, oc1);
    out[p0 + 2*TQ  ] = make_float2(ts2, oc2);
    out[p0 + 3*TQ  ] = make_float2(ts3, oc3);
}

// ---------------- launch ----------------
extern "C" void kernel_launch(void* const* d_in, const int* in_sizes, int n_in,
                              void* d_out, int out_size)
{
    const float *pre_feat = nullptr, *feats = nullptr, *KRcam = nullptr,
                *origin = nullptr, *w2ac = nullptr, *W_sp = nullptr,
                *b_sp = nullptr, *W_t = nullptr, *b_t = nullptr,
                *W_o = nullptr, *b_o = nullptr;
    const int* pre_coords = nullptr;
    int n24 = 0, n1 = 0;

    for (int i = 0; i < n_in; i++) {
        int s = in_sizes[i];
        const void* p = d_in[i];
        switch (s) {
            case MPTS * CPRE:  pre_feat   = (const float*)p; break;
            case MPTS * 4:     pre_coords = (const int*)p;   break;
            case VHW * NC:     feats      = (const float*)p; break;
            case NV * 16:      KRcam      = (const float*)p; break;
            case 3:            origin     = (const float*)p; break;
            case 16:           w2ac       = (const float*)p; break;
            case CIN * CHID:   W_sp       = (const float*)p; break;
            case 24:
                if (n24 == 0) b_sp = (const float*)p;
                else if (n24 == 1) W_t = (const float*)p;
                else W_o = (const float*)p;
                n24++; break;
            case 1:
                if (n1 == 0) b_t = (const float*)p;
                else b_o = (const float*)p;
                n1++; break;
            default: break;
        }
    }

    k_transpose<<<(VHW * 3 + 255) / 256, 256>>>(feats);
    k_backproject<<<NPTS / 256, 256>>>(pre_coords, KRcam, origin, w2ac, (float*)d_out);
    k_mlp<<<TQ / 128, 128>>>(pre_feat, W_sp, b_sp, W_t, b_t, W_o, b_o, (float*)d_out);
}

// round 10
// speedup vs baseline: 1.5394x; 1.5394x over previous
#include <cuda_runtime.h>
#include <math.h>

// ---------------- problem constants ----------------
#define MPTS   32768
#define NPTS   (MPTS * 8)          // 262144 upsampled points
#define NV     9
#define NC     24
#define NH     120
#define NW     160
#define CPRE   50
#define CIN    (NC + 1 + CPRE)     // 75
#define CHID   24
#define HW     (NH * NW)
#define VHW    (NV * HW)
#define VOXSZ  0.04f
#define NP2    (NPTS / 2)          // MLP: 131072 threads, 2 points each

// ---------------- scratch (device globals; no allocation) ----------------
__device__ __align__(16) float  g_featT[VHW * NC];      // feats transposed to (V,H,W,C) fp32
__device__ __align__(16) float  g_features[NPTS * NC];  // per-point mean features
__device__ float  g_z[NPTS];
__device__ double g_red[3];                             // sum(z*pos), sum(z^2*pos), sum(pos)

__constant__ int c_off[8][3] = {
    {0,0,0},{1,0,0},{0,1,0},{0,0,1},{1,1,0},{1,0,1},{0,1,1},{1,1,1}
};

// ---------------- kernel 1: transpose (V,C,H,W) -> (V,H,W,C); zero g_red ----------------
// 2 threads per pixel, 12 channels each -> three float4 stores per thread.
__global__ void k_transpose(const float* __restrict__ feats) {
    int tid = blockIdx.x * blockDim.x + threadIdx.x;
    if (tid == 0) { g_red[0] = 0.0; g_red[1] = 0.0; g_red[2] = 0.0; }
    if (tid >= VHW * 2) return;
    int pix = tid >> 1;
    int c0  = (tid & 1) * 12;
    int v   = pix / HW;
    int rem = pix - v * HW;
    const float* src = feats + (size_t)v * NC * HW + (size_t)c0 * HW + rem;
    float vals[12];
#pragma unroll
    for (int c = 0; c < 12; c++) vals[c] = src[(size_t)c * HW];   // coalesced across x
    float4* dst = reinterpret_cast<float4*>(g_featT) + (size_t)pix * 6 + (c0 >> 2);
    dst[0] = make_float4(vals[0], vals[1], vals[2],  vals[3]);
    dst[1] = make_float4(vals[4], vals[5], vals[6],  vals[7]);
    dst[2] = make_float4(vals[8], vals[9], vals[10], vals[11]);
}

// ---------------- kernel 2: back-projection + per-point stats (R1 known-good) ----------------
__global__ __launch_bounds__(256) void k_backproject(
    const int*   __restrict__ pre_coords,   // (M,4) int32
    const float* __restrict__ KRcam,        // (V,1,4,4)
    const float* __restrict__ origin,       // (3,)
    const float* __restrict__ w2ac,         // (1,4,4)
    float*       __restrict__ d_out)        // [out 2N | count N | r_coords 4N]
{
    __shared__ float sKR[NV * 16];
    __shared__ float sW2[12];
    __shared__ float sOrg[3];
    int t = threadIdx.x;
    if (t < NV * 16) sKR[t] = KRcam[t];
    if (t < 12)      sW2[t] = w2ac[t];
    if (t < 3)       sOrg[t] = origin[t];
    __syncthreads();

    int n = blockIdx.x * 256 + t;
    int m = n >> 3, k = n & 7;

    int cx = pre_coords[m * 4 + 1] + c_off[k][0];
    int cy = pre_coords[m * 4 + 2] + c_off[k][1];
    int cz = pre_coords[m * 4 + 3] + c_off[k][2];
    float wx = (float)cx * VOXSZ + sOrg[0];
    float wy = (float)cy * VOXSZ + sOrg[1];
    float wz = (float)cz * VOXSZ + sOrg[2];

    // r_coords
    {
        float4 rc;
        rc.x = sW2[0]*wx + sW2[1]*wy + sW2[2]*wz + sW2[3];
        rc.y = sW2[4]*wx + sW2[5]*wy + sW2[6]*wz + sW2[7];
        rc.z = sW2[8]*wx + sW2[9]*wy + sW2[10]*wz + sW2[11];
        rc.w = 0.0f;
        reinterpret_cast<float4*>(d_out + 3 * NPTS)[n] = rc;
    }

    float4 acc[6];
#pragma unroll
    for (int j = 0; j < 6; j++) acc[j] = make_float4(0.f, 0.f, 0.f, 0.f);
    float zsum = 0.f;
    int   cnt  = 0;

    const float4* base = reinterpret_cast<const float4*>(g_featT);

#pragma unroll 1
    for (int v = 0; v < NV; v++) {
        const float* R = sKR + v * 16;
        float ix = R[0]*wx + R[1]*wy + R[2]*wz  + R[3];
        float iy = R[4]*wx + R[5]*wy + R[6]*wz  + R[7];
        float iz = R[8]*wx + R[9]*wy + R[10]*wz + R[11];
        float sz = (fabsf(iz) > 1e-9f) ? iz : 1e-9f;
        float px = ix / sz;
        float py = iy / sz;
        bool msk = (px >= 0.f) && (px <= (float)(NW - 1)) &&
                   (py >= 0.f) && (py <= (float)(NH - 1)) && (iz > 0.f);
        if (!msk) continue;

        float fx0 = floorf(px), fy0 = floorf(py);
        float ax = px - fx0,    ay = py - fy0;
        int ix0 = (int)fx0,     iy0 = (int)fy0;
        int ix1 = ix0 + 1,      iy1 = iy0 + 1;
        float okx = (ix1 < NW) ? 1.f : 0.f;
        float oky = (iy1 < NH) ? 1.f : 0.f;
        ix1 = min(ix1, NW - 1); iy1 = min(iy1, NH - 1);

        float w00 = (1.f - ax) * (1.f - ay);
        float w10 = ax * (1.f - ay) * okx;
        float w01 = (1.f - ax) * ay * oky;
        float w11 = ax * ay * okx * oky;

        int b00 = ((v * NH + iy0) * NW + ix0) * 6;
        int b10 = ((v * NH + iy0) * NW + ix1) * 6;
        int b01 = ((v * NH + iy1) * NW + ix0) * 6;
        int b11 = ((v * NH + iy1) * NW + ix1) * 6;

#pragma unroll
        for (int j = 0; j < 6; j++) {
            float4 c00 = base[b00 + j];
            float4 c10 = base[b10 + j];
            float4 c01 = base[b01 + j];
            float4 c11 = base[b11 + j];
            acc[j].x += w00*c00.x + w10*c10.x + w01*c01.x + w11*c11.x;
            acc[j].y += w00*c00.y + w10*c10.y + w01*c01.y + w11*c11.y;
            acc[j].z += w00*c00.z + w10*c10.z + w01*c01.z + w11*c11.z;
            acc[j].w += w00*c00.w + w10*c10.w + w01*c01.w + w11*c11.w;
        }
        zsum += iz;
        cnt  += 1;
    }

    float denom = fmaxf((float)cnt, 1.f);
    float inv   = 1.f / denom;
    float4* fdst = reinterpret_cast<float4*>(g_features) + (size_t)n * 6;
#pragma unroll
    for (int j = 0; j < 6; j++) {
        float4 a = acc[j];
        fdst[j] = make_float4(a.x * inv, a.y * inv, a.z * inv, a.w * inv);
    }
    float zv = zsum * inv;
    g_z[n] = zv;
    d_out[2 * NPTS + n] = (float)cnt;

    bool  pos = zv > 0.f;
    float r0 = pos ? zv : 0.f;
    float r1 = pos ? zv * zv : 0.f;
    float r2 = pos ? 1.f : 0.f;
#pragma unroll
    for (int o = 16; o > 0; o >>= 1) {
        r0 += __shfl_down_sync(0xffffffffu, r0, o);
        r1 += __shfl_down_sync(0xffffffffu, r1, o);
        r2 += __shfl_down_sync(0xffffffffu, r2, o);
    }
    __shared__ float s0[8], s1[8], s2[8];
    int w = t >> 5, lane = t & 31;
    if (lane == 0) { s0[w] = r0; s1[w] = r1; s2[w] = r2; }
    __syncthreads();
    if (t == 0) {
        float t0 = 0.f, t1 = 0.f, t2 = 0.f;
#pragma unroll
        for (int i = 0; i < 8; i++) { t0 += s0[i]; t1 += s1[i]; t2 += s2[i]; }
        atomicAdd(&g_red[0], (double)t0);
        atomicAdd(&g_red[1], (double)t1);
        atomicAdd(&g_red[2], (double)t2);
    }
}

// ---------------- kernel 3: z-norm + MLP heads (2 points/thread, scalar FFMA) ----------------
__device__ __forceinline__ void fma_row2(float* h0, float* h1, float f0, float f1,
                                         const float4* __restrict__ wr) {
#pragma unroll
    for (int q = 0; q < 6; q++) {
        float4 w = wr[q];
        h0[4*q+0] += f0 * w.x;  h1[4*q+0] += f1 * w.x;
        h0[4*q+1] += f0 * w.y;  h1[4*q+1] += f1 * w.y;
        h0[4*q+2] += f0 * w.z;  h1[4*q+2] += f1 * w.z;
        h0[4*q+3] += f0 * w.w;  h1[4*q+3] += f1 * w.w;
    }
}

__global__ __launch_bounds__(256) void k_mlp(
    const float* __restrict__ pre_feat,
    const float* __restrict__ W_sp,
    const float* __restrict__ b_sp,
    const float* __restrict__ W_t,
    const float* __restrict__ b_t,
    const float* __restrict__ W_o,
    const float* __restrict__ b_o,
    float*       __restrict__ d_out)
{
    __shared__ float4 sW[CIN * 6];
    __shared__ float  sWt[CHID], sWo[CHID], sB[CHID];
    int t = threadIdx.x;
    const float4* Wv = reinterpret_cast<const float4*>(W_sp);
    for (int i = t; i < CIN * 6; i += 256) sW[i] = Wv[i];
    if (t < CHID) { sWt[t] = W_t[t]; sWo[t] = W_o[t]; sB[t] = b_sp[t]; }
    __syncthreads();

    double npos  = fmax(g_red[2], 1.0);
    double zmean = g_red[0] / npos;
    double var   = g_red[1] - zmean * zmean * npos;
    float  znorm = (float)sqrt(fmax(var, 0.0)) + 1e-5f;
    float  zmf   = (float)zmean;

    int p0 = blockIdx.x * 256 + t;       // also handles p0 + NP2

    float h0[CHID], h1[CHID];
#pragma unroll
    for (int j = 0; j < CHID; j++) { h0[j] = sB[j]; h1[j] = sB[j]; }

    // features (channels 0..23)
    const float4* f0 = reinterpret_cast<const float4*>(g_features) + (size_t)p0 * 6;
    const float4* f1 = f0 + (size_t)NP2 * 6;
#pragma unroll
    for (int j4 = 0; j4 < 6; j4++) {
        float4 F0 = f0[j4], F1 = f1[j4];
        fma_row2(h0, h1, F0.x, F1.x, sW + (4*j4+0)*6);
        fma_row2(h0, h1, F0.y, F1.y, sW + (4*j4+1)*6);
        fma_row2(h0, h1, F0.z, F1.z, sW + (4*j4+2)*6);
        fma_row2(h0, h1, F0.w, F1.w, sW + (4*j4+3)*6);
    }
    // zn (channel 24)
    {
        float z0 = g_z[p0], z1 = g_z[p0 + NP2];
        float n0 = (z0 > 0.f) ? (z0 - zmf) / znorm : 0.f;
        float n1 = (z1 > 0.f) ? (z1 - zmf) / znorm : 0.f;
        fma_row2(h0, h1, n0, n1, sW + NC * 6);
    }
    // pre_feat (channels 25..74)
    {
        const float2* q0 = reinterpret_cast<const float2*>(pre_feat + (size_t)( p0        >> 3) * CPRE);
        const float2* q1 = reinterpret_cast<const float2*>(pre_feat + (size_t)((p0 + NP2) >> 3) * CPRE);
#pragma unroll
        for (int i = 0; i < CPRE / 2; i++) {
            float2 g0 = q0[i], g1 = q1[i];
            fma_row2(h0, h1, g0.x, g1.x, sW + (NC + 1 + 2*i + 0) * 6);
            fma_row2(h0, h1, g0.y, g1.y, sW + (NC + 1 + 2*i + 1) * 6);
        }
    }

    // relu + heads
    float bt = b_t[0], bo = b_o[0];
    float ts0 = bt, ts1 = bt, oc0 = bo, oc1 = bo;
#pragma unroll
    for (int j = 0; j < CHID; j++) {
        float v0 = fmaxf(h0[j], 0.f), v1 = fmaxf(h1[j], 0.f);
        float wt = sWt[j], wo = sWo[j];
        ts0 += v0 * wt; ts1 += v1 * wt;
        oc0 += v0 * wo; oc1 += v1 * wo;
    }
    float2* out = reinterpret_cast<float2*>(d_out);
    out[p0      ] = make_float2(ts0, oc0);
    out[p0 + NP2] = make_float2(ts1, oc1);
}

// ---------------- launch ----------------
extern "C" void kernel_launch(void* const* d_in, const int* in_sizes, int n_in,
                              void* d_out, int out_size)
{
    const float *pre_feat = nullptr, *feats = nullptr, *KRcam = nullptr,
                *origin = nullptr, *w2ac = nullptr, *W_sp = nullptr,
                *b_sp = nullptr, *W_t = nullptr, *b_t = nullptr,
                *W_o = nullptr, *b_o = nullptr;
    const int* pre_coords = nullptr;
    int n24 = 0, n1 = 0;

    for (int i = 0; i < n_in; i++) {
        int s = in_sizes[i];
        const void* p = d_in[i];
        switch (s) {
            case MPTS * CPRE:  pre_feat   = (const float*)p; break;
            case MPTS * 4:     pre_coords = (const int*)p;   break;
            case VHW * NC:     feats      = (const float*)p; break;
            case NV * 16:      KRcam      = (const float*)p; break;
            case 3:            origin     = (const float*)p; break;
            case 16:           w2ac       = (const float*)p; break;
            case CIN * CHID:   W_sp       = (const float*)p; break;
            case 24:
                if (n24 == 0) b_sp = (const float*)p;
                else if (n24 == 1) W_t = (const float*)p;
                else W_o = (const float*)p;
                n24++; break;
            case 1:
                if (n1 == 0) b_t = (const float*)p;
                else b_o = (const float*)p;
                n1++; break;
            default: break;
        }
    }

    k_transpose<<<(VHW * 2 + 255) / 256, 256>>>(feats);
    k_backproject<<<NPTS / 256, 256>>>(pre_coords, KRcam, origin, w2ac, (float*)d_out);
    k_mlp<<<NP2 / 256, 256>>>(pre_feat, W_sp, b_sp, W_t, b_t, W_o, b_o, (float*)d_out);
}

// round 12
// speedup vs baseline: 2.1785x; 1.4151x over previous
#include <cuda_runtime.h>
#include <cuda_fp16.h>
#include <math.h>

// ---------------- problem constants ----------------
#define MPTS   32768
#define NPTS   (MPTS * 8)          // 262144 upsampled points
#define NV     9
#define NC     24
#define NH     120
#define NW     160
#define CPRE   50
#define CIN    (NC + 1 + CPRE)     // 75
#define CHID   24
#define HW     (NH * NW)
#define VHW    (NV * HW)
#define VOXSZ  0.04f
#define NP2    (NPTS / 2)          // MLP: 131072 threads, 2 points each

// ---------------- scratch (device globals; no allocation) ----------------
__device__ __align__(16) __half g_featTh[VHW * NC + 64];  // feats (V,H,W,C) fp16, +pad
__device__ __align__(16) float  g_features[NPTS * NC];    // per-point mean features
__device__ float  g_z[NPTS];
__device__ double g_red[3];                               // sum(z*pos), sum(z^2*pos), sum(pos)

__constant__ int c_off[8][3] = {
    {0,0,0},{1,0,0},{0,1,0},{0,0,1},{1,1,0},{1,0,1},{0,1,1},{1,1,1}
};

// reinterpret u32 as __half2 (scalar bit-cast; register-resident)
__device__ __forceinline__ __half2 u2h(unsigned u) {
    __half2 h;
    *reinterpret_cast<unsigned*>(&h) = u;
    return h;
}

// ---------------- kernel 1: transpose (V,C,H,W) fp32 -> (V,H,W,C) fp16; zero g_red ----------------
// 3 threads per pixel, 8 channels each -> one uint4 store per thread. (R4/R5: 7.3us measured)
__global__ void k_transpose(const float* __restrict__ feats) {
    int tid = blockIdx.x * blockDim.x + threadIdx.x;
    if (tid == 0) { g_red[0] = 0.0; g_red[1] = 0.0; g_red[2] = 0.0; }
    if (tid >= VHW * 3) return;
    int pix = tid / 3;
    int c0  = (tid - pix * 3) * 8;
    int v   = pix / HW;
    int rem = pix - v * HW;
    const float* src = feats + (size_t)v * NC * HW + (size_t)c0 * HW + rem;
    float vals[8];
#pragma unroll
    for (int c = 0; c < 8; c++) vals[c] = src[(size_t)c * HW];   // coalesced across x
    __half2 h[4];
#pragma unroll
    for (int j = 0; j < 4; j++) h[j] = __floats2half2_rn(vals[2*j], vals[2*j+1]);
    reinterpret_cast<uint4*>(g_featTh)[pix * 3 + (c0 >> 3)] = *reinterpret_cast<uint4*>(h);
}

// ---------------- kernel 2: back-projection + per-point stats (fp16 spans, HFMA2) ----------------
__global__ __launch_bounds__(256) void k_backproject(
    const int*   __restrict__ pre_coords,   // (M,4) int32
    const float* __restrict__ KRcam,        // (V,1,4,4)
    const float* __restrict__ origin,       // (3,)
    const float* __restrict__ w2ac,         // (1,4,4)
    float*       __restrict__ d_out)        // [out 2N | count N | r_coords 4N]
{
    __shared__ float sKR[NV * 16];
    __shared__ float sW2[12];
    __shared__ float sOrg[3];
    int t = threadIdx.x;
    if (t < NV * 16) sKR[t] = KRcam[t];
    if (t < 12)      sW2[t] = w2ac[t];
    if (t < 3)       sOrg[t] = origin[t];
    __syncthreads();

    int n = blockIdx.x * 256 + t;
    int m = n >> 3, k = n & 7;

    int cx = pre_coords[m * 4 + 1] + c_off[k][0];
    int cy = pre_coords[m * 4 + 2] + c_off[k][1];
    int cz = pre_coords[m * 4 + 3] + c_off[k][2];
    float wx = (float)cx * VOXSZ + sOrg[0];
    float wy = (float)cy * VOXSZ + sOrg[1];
    float wz = (float)cz * VOXSZ + sOrg[2];

    // r_coords
    {
        float4 rc;
        rc.x = sW2[0]*wx + sW2[1]*wy + sW2[2]*wz + sW2[3];
        rc.y = sW2[4]*wx + sW2[5]*wy + sW2[6]*wz + sW2[7];
        rc.z = sW2[8]*wx + sW2[9]*wy + sW2[10]*wz + sW2[11];
        rc.w = 0.0f;
        reinterpret_cast<float4*>(d_out + 3 * NPTS)[n] = rc;
    }

    float a[NC];
#pragma unroll
    for (int j = 0; j < NC; j++) a[j] = 0.f;
    float zsum = 0.f;
    int   cnt  = 0;

    const uint4* fb = reinterpret_cast<const uint4*>(g_featTh);

#pragma unroll 1
    for (int v = 0; v < NV; v++) {
        const float* R = sKR + v * 16;
        float ix = R[0]*wx + R[1]*wy + R[2]*wz  + R[3];
        float iy = R[4]*wx + R[5]*wy + R[6]*wz  + R[7];
        float iz = R[8]*wx + R[9]*wy + R[10]*wz + R[11];
        float sz = (fabsf(iz) > 1e-9f) ? iz : 1e-9f;
        float px = ix / sz;
        float py = iy / sz;
        bool msk = (px >= 0.f) && (px <= (float)(NW - 1)) &&
                   (py >= 0.f) && (py <= (float)(NH - 1)) && (iz > 0.f);
        if (!msk) continue;

        float fx0 = floorf(px), fy0 = floorf(py);
        float ax = px - fx0,    ay = py - fy0;
        int ix0 = (int)fx0,     iy0 = (int)fy0;
        float okx = (ix0 + 1 < NW) ? 1.f : 0.f;
        float oky = (iy0 + 1 < NH) ? 1.f : 0.f;
        int iy1 = min(iy0 + 1, NH - 1);

        // bilinear weights -> half2 (4 small converts per view)
        __half2 W00 = __float2half2_rn((1.f - ax) * (1.f - ay));
        __half2 W10 = __float2half2_rn(ax * (1.f - ay) * okx);
        __half2 W01 = __float2half2_rn((1.f - ax) * ay * oky);
        __half2 W11 = __float2half2_rn(ax * ay * okx * oky);

        // contiguous 96B span covers both x0 and x1 (pixel = 48B fp16)
        int b_top = ((v * NH + iy0) * NW + ix0) * 3;
        int b_bot = ((v * NH + iy1) * NW + ix0) * 3;

#pragma unroll
        for (int j = 0; j < 3; j++) {               // channels 8j..8j+7
            uint4 T0 = fb[b_top + j];               // x0
            uint4 T1 = fb[b_top + j + 3];           // x1
            uint4 B0 = fb[b_bot + j];
            uint4 B1 = fb[b_bot + j + 3];
            int cb = 8 * j;
            // weighted sum entirely in half pipe (HMUL2/HFMA2, full rate)
            __half2 r0 = __hmul2(u2h(T0.x), W00);
            r0 = __hfma2(u2h(T1.x), W10, r0);
            r0 = __hfma2(u2h(B0.x), W01, r0);
            r0 = __hfma2(u2h(B1.x), W11, r0);
            __half2 r1 = __hmul2(u2h(T0.y), W00);
            r1 = __hfma2(u2h(T1.y), W10, r1);
            r1 = __hfma2(u2h(B0.y), W01, r1);
            r1 = __hfma2(u2h(B1.y), W11, r1);
            __half2 r2 = __hmul2(u2h(T0.z), W00);
            r2 = __hfma2(u2h(T1.z), W10, r2);
            r2 = __hfma2(u2h(B0.z), W01, r2);
            r2 = __hfma2(u2h(B1.z), W11, r2);
            __half2 r3 = __hmul2(u2h(T0.w), W00);
            r3 = __hfma2(u2h(T1.w), W10, r3);
            r3 = __hfma2(u2h(B0.w), W01, r3);
            r3 = __hfma2(u2h(B1.w), W11, r3);
            // single convert of the per-view result, fp32 accumulate
            float2 f0 = __half22float2(r0);
            float2 f1 = __half22float2(r1);
            float2 f2 = __half22float2(r2);
            float2 f3 = __half22float2(r3);
            a[cb+0] += f0.x;  a[cb+1] += f0.y;
            a[cb+2] += f1.x;  a[cb+3] += f1.y;
            a[cb+4] += f2.x;  a[cb+5] += f2.y;
            a[cb+6] += f3.x;  a[cb+7] += f3.y;
        }
        zsum += iz;
        cnt  += 1;
    }

    float denom = fmaxf((float)cnt, 1.f);
    float inv   = 1.f / denom;
    float4* fdst = reinterpret_cast<float4*>(g_features) + (size_t)n * 6;
#pragma unroll
    for (int j = 0; j < 6; j++)
        fdst[j] = make_float4(a[4*j]*inv, a[4*j+1]*inv, a[4*j+2]*inv, a[4*j+3]*inv);

    float zv = zsum * inv;
    g_z[n] = zv;
    d_out[2 * NPTS + n] = (float)cnt;

    bool  pos = zv > 0.f;
    float r0 = pos ? zv : 0.f;
    float r1 = pos ? zv * zv : 0.f;
    float r2 = pos ? 1.f : 0.f;
#pragma unroll
    for (int o = 16; o > 0; o >>= 1) {
        r0 += __shfl_down_sync(0xffffffffu, r0, o);
        r1 += __shfl_down_sync(0xffffffffu, r1, o);
        r2 += __shfl_down_sync(0xffffffffu, r2, o);
    }
    __shared__ float s0[8], s1[8], s2[8];
    int w = t >> 5, lane = t & 31;
    if (lane == 0) { s0[w] = r0; s1[w] = r1; s2[w] = r2; }
    __syncthreads();
    if (t == 0) {
        float t0 = 0.f, t1 = 0.f, t2 = 0.f;
#pragma unroll
        for (int i = 0; i < 8; i++) { t0 += s0[i]; t1 += s1[i]; t2 += s2[i]; }
        atomicAdd(&g_red[0], (double)t0);
        atomicAdd(&g_red[1], (double)t1);
        atomicAdd(&g_red[2], (double)t2);
    }
}

// ---------------- kernel 3: z-norm + MLP heads (2 points/thread, scalar FFMA; R10 proven) ----------------
__device__ __forceinline__ void fma_row2(float* h0, float* h1, float f0, float f1,
                                         const float4* __restrict__ wr) {
#pragma unroll
    for (int q = 0; q < 6; q++) {
        float4 w = wr[q];
        h0[4*q+0] += f0 * w.x;  h1[4*q+0] += f1 * w.x;
        h0[4*q+1] += f0 * w.y;  h1[4*q+1] += f1 * w.y;
        h0[4*q+2] += f0 * w.z;  h1[4*q+2] += f1 * w.z;
        h0[4*q+3] += f0 * w.w;  h1[4*q+3] += f1 * w.w;
    }
}

__global__ __launch_bounds__(256) void k_mlp(
    const float* __restrict__ pre_feat,
    const float* __restrict__ W_sp,
    const float* __restrict__ b_sp,
    const float* __restrict__ W_t,
    const float* __restrict__ b_t,
    const float* __restrict__ W_o,
    const float* __restrict__ b_o,
    float*       __restrict__ d_out)
{
    __shared__ float4 sW[CIN * 6];
    __shared__ float  sWt[CHID], sWo[CHID], sB[CHID];
    int t = threadIdx.x;
    const float4* Wv = reinterpret_cast<const float4*>(W_sp);
    for (int i = t; i < CIN * 6; i += 256) sW[i] = Wv[i];
    if (t < CHID) { sWt[t] = W_t[t]; sWo[t] = W_o[t]; sB[t] = b_sp[t]; }
    __syncthreads();

    double npos  = fmax(g_red[2], 1.0);
    double zmean = g_red[0] / npos;
    double var   = g_red[1] - zmean * zmean * npos;
    float  znorm = (float)sqrt(fmax(var, 0.0)) + 1e-5f;
    float  zmf   = (float)zmean;

    int p0 = blockIdx.x * 256 + t;       // also handles p0 + NP2

    float h0[CHID], h1[CHID];
#pragma unroll
    for (int j = 0; j < CHID; j++) { h0[j] = sB[j]; h1[j] = sB[j]; }

    // features (channels 0..23)
    const float4* f0 = reinterpret_cast<const float4*>(g_features) + (size_t)p0 * 6;
    const float4* f1 = f0 + (size_t)NP2 * 6;
#pragma unroll
    for (int j4 = 0; j4 < 6; j4++) {
        float4 F0 = f0[j4], F1 = f1[j4];
        fma_row2(h0, h1, F0.x, F1.x, sW + (4*j4+0)*6);
        fma_row2(h0, h1, F0.y, F1.y, sW + (4*j4+1)*6);
        fma_row2(h0, h1, F0.z, F1.z, sW + (4*j4+2)*6);
        fma_row2(h0, h1, F0.w, F1.w, sW + (4*j4+3)*6);
    }
    // zn (channel 24)
    {
        float z0 = g_z[p0], z1 = g_z[p0 + NP2];
        float n0 = (z0 > 0.f) ? (z0 - zmf) / znorm : 0.f;
        float n1 = (z1 > 0.f) ? (z1 - zmf) / znorm : 0.f;
        fma_row2(h0, h1, n0, n1, sW + NC * 6);
    }
    // pre_feat (channels 25..74)
    {
        const float2* q0 = reinterpret_cast<const float2*>(pre_feat + (size_t)( p0        >> 3) * CPRE);
        const float2* q1 = reinterpret_cast<const float2*>(pre_feat + (size_t)((p0 + NP2) >> 3) * CPRE);
#pragma unroll
        for (int i = 0; i < CPRE / 2; i++) {
            float2 g0 = q0[i], g1 = q1[i];
            fma_row2(h0, h1, g0.x, g1.x, sW + (NC + 1 + 2*i + 0) * 6);
            fma_row2(h0, h1, g0.y, g1.y, sW + (NC + 1 + 2*i + 1) * 6);
        }
    }

    // relu + heads
    float bt = b_t[0], bo = b_o[0];
    float ts0 = bt, ts1 = bt, oc0 = bo, oc1 = bo;
#pragma unroll
    for (int j = 0; j < CHID; j++) {
        float v0 = fmaxf(h0[j], 0.f), v1 = fmaxf(h1[j], 0.f);
        float wt = sWt[j], wo = sWo[j];
        ts0 += v0 * wt; ts1 += v1 * wt;
        oc0 += v0 * wo; oc1 += v1 * wo;
    }
    float2* out = reinterpret_cast<float2*>(d_out);
    out[p0      ] = make_float2(ts0, oc0);
    out[p0 + NP2] = make_float2(ts1, oc1);
}

// ---------------- launch ----------------
extern "C" void kernel_launch(void* const* d_in, const int* in_sizes, int n_in,
                              void* d_out, int out_size)
{
    const float *pre_feat = nullptr, *feats = nullptr, *KRcam = nullptr,
                *origin = nullptr, *w2ac = nullptr, *W_sp = nullptr,
                *b_sp = nullptr, *W_t = nullptr, *b_t = nullptr,
                *W_o = nullptr, *b_o = nullptr;
    const int* pre_coords = nullptr;
    int n24 = 0, n1 = 0;

    for (int i = 0; i < n_in; i++) {
        int s = in_sizes[i];
        const void* p = d_in[i];
        switch (s) {
            case MPTS * CPRE:  pre_feat   = (const float*)p; break;
            case MPTS * 4:     pre_coords = (const int*)p;   break;
            case VHW * NC:     feats      = (const float*)p; break;
            case NV * 16:      KRcam      = (const float*)p; break;
            case 3:            origin     = (const float*)p; break;
            case 16:           w2ac       = (const float*)p; break;
            case CIN * CHID:   W_sp       = (const float*)p; break;
            case 24:
                if (n24 == 0) b_sp = (const float*)p;
                else if (n24 == 1) W_t = (const float*)p;
                else W_o = (const float*)p;
                n24++; break;
            case 1:
                if (n1 == 0) b_t = (const float*)p;
                else b_o = (const float*)p;
                n1++; break;
            default: break;
        }
    }

    k_transpose<<<(VHW * 3 + 255) / 256, 256>>>(feats);
    k_backproject<<<NPTS / 256, 256>>>(pre_coords, KRcam, origin, w2ac, (float*)d_out);
    k_mlp<<<NP2 / 256, 256>>>(pre_feat, W_sp, b_sp, W_t, b_t, W_o, b_o, (float*)d_out);
}